// round 14
// baseline (speedup 1.0000x reference)
#include <cuda_runtime.h>
#include <cuda_bf16.h>
#include <cstdint>

// Problem dims
#define BDIM 32
#define CDIM 256
#define FDIM 2048
constexpr int NTOT = BDIM * CDIM * FDIM;          // 16,777,216
constexpr int N4 = NTOT / 4;                       // 4,194,304 float4s per tensor
constexpr int G1 = 2048;                           // k_phase grid
constexpr int T1 = 256;                            // k_phase block
constexpr int GM = 1024;                           // k_mag grid
constexpr int NOFF = 6;                            // off-diag pairs per batch
constexpr int NDIA = 4;                            // diag pairs per batch
constexpr int GOFF = BDIM * NOFF;                  // 192 off-diag blocks (first)
constexpr int G2 = BDIM * (NOFF + NDIA);           // 320 gemm blocks

// Scratch (device globals: allocation-free; 16B-aligned for float4 reduction)
__device__ __nv_bfloat16 g_c[NTOT];                // cos(phase_hat) bf16
__device__ __nv_bfloat16 g_s[NTOT];                // sin(phase_hat) bf16
__device__ __align__(16) float g_magp[GM];
__device__ __align__(16) float g_php[G1];
__device__ __align__(16) float g_cohp[G2];

__constant__ int c_opi[NOFF] = {0,0,0,1,1,2};
__constant__ int c_opj[NOFF] = {1,2,3,2,3,3};

// ---------------------------------------------------------------------------
// Stream/event plumbing (static-init; capture-safe fork/join)
// ---------------------------------------------------------------------------
struct OverlapRes {
    cudaStream_t s2;
    cudaEvent_t evPhase, evJoin;
    OverlapRes() {
        cudaStreamCreateWithFlags(&s2, cudaStreamNonBlocking);
        cudaEventCreateWithFlags(&evPhase, cudaEventDisableTiming);
        cudaEventCreateWithFlags(&evJoin, cudaEventDisableTiming);
    }
};
static OverlapRes g_res;

// ---------------------------------------------------------------------------
// Kernel 1a: phase loss + cos/sin scratch (HBM-bound, ~192MB)
// ---------------------------------------------------------------------------
__global__ void __launch_bounds__(T1) k_phase(
    const float4* __restrict__ ph, const float4* __restrict__ pt)
{
    int tid = blockIdx.x * T1 + threadIdx.x;
    const int stride = G1 * T1;
    float sp = 0.f;
    uint2* gc = reinterpret_cast<uint2*>(g_c);
    uint2* gs = reinterpret_cast<uint2*>(g_s);
#pragma unroll
    for (int i = 0; i < 8; i++) {
        int idx = tid + i * stride;
        float4 p = ph[idx], q = pt[idx];
        sp += 4.f - __cosf(p.x - q.x) - __cosf(p.y - q.y)
                  - __cosf(p.z - q.z) - __cosf(p.w - q.w);
        float s0, c0, s1, c1, s2, c2, s3, c3;
        __sincosf(p.x, &s0, &c0); __sincosf(p.y, &s1, &c1);
        __sincosf(p.z, &s2, &c2); __sincosf(p.w, &s3, &c3);
        __nv_bfloat162 hc0 = __floats2bfloat162_rn(c0, c1);
        __nv_bfloat162 hc1 = __floats2bfloat162_rn(c2, c3);
        __nv_bfloat162 hs0 = __floats2bfloat162_rn(s0, s1);
        __nv_bfloat162 hs1 = __floats2bfloat162_rn(s2, s3);
        gc[idx] = make_uint2(*reinterpret_cast<unsigned*>(&hc0),
                             *reinterpret_cast<unsigned*>(&hc1));
        gs[idx] = make_uint2(*reinterpret_cast<unsigned*>(&hs0),
                             *reinterpret_cast<unsigned*>(&hs1));
    }
#pragma unroll
    for (int o = 16; o; o >>= 1) sp += __shfl_xor_sync(0xffffffffu, sp, o);
    __shared__ float rp[8];
    int w = threadIdx.x >> 5;
    if ((threadIdx.x & 31) == 0) rp[w] = sp;
    __syncthreads();
    if (threadIdx.x == 0) {
        float b = 0.f;
#pragma unroll
        for (int i = 0; i < 8; i++) b += rp[i];
        g_php[blockIdx.x] = b;
    }
}

// ---------------------------------------------------------------------------
// Kernel 1b: mag MSE (pure DRAM; runs concurrently with k_gemm on stream s2)
// ---------------------------------------------------------------------------
__global__ void __launch_bounds__(T1) k_mag(
    const float4* __restrict__ mh, const float4* __restrict__ mt)
{
    int tid = blockIdx.x * T1 + threadIdx.x;
    const int stride = GM * T1;                    // 262144
    float sm = 0.f;
#pragma unroll
    for (int i = 0; i < 16; i++) {
        int idx = tid + i * stride;
        float4 a = mh[idx], b = mt[idx];
        float d0 = a.x - b.x, d1 = a.y - b.y, d2 = a.z - b.z, d3 = a.w - b.w;
        sm += d0 * d0 + d1 * d1 + d2 * d2 + d3 * d3;
    }
#pragma unroll
    for (int o = 16; o; o >>= 1) sm += __shfl_xor_sync(0xffffffffu, sm, o);
    __shared__ float rm[8];
    int w = threadIdx.x >> 5;
    if ((threadIdx.x & 31) == 0) rm[w] = sm;
    __syncthreads();
    if (threadIdx.x == 0) {
        float a = 0.f;
#pragma unroll
        for (int i = 0; i < 8; i++) a += rm[i];
        g_magp[blockIdx.x] = a;
    }
}

// ---------------------------------------------------------------------------
// Kernel 2: Gauss 3-mult symmetric-pair batched GEMM (bf16 mma.sync)
//   KC=64, 3-stage dynamic-smem cp.async pipeline, off-diag-first ordering.
// ---------------------------------------------------------------------------
#define KC 64
#define TILE 64
#define ROWSTRIDE 72                               // bf16 elems per smem row (128B + 16B pad)
#define TILEBYTES (TILE * ROWSTRIDE * 2)           // 9216
#define STAGEBYTES (4 * TILEBYTES)                 // 36864
#define NSTAGE 3
#define SMEM_DYN (NSTAGE * STAGEBYTES)             // 110592

__device__ __forceinline__ void cp_async16(void* smem, const void* gmem) {
    unsigned s = (unsigned)__cvta_generic_to_shared(smem);
    asm volatile("cp.async.cg.shared.global [%0], [%1], 16;\n" :: "r"(s), "l"(gmem));
}
#define CP_COMMIT asm volatile("cp.async.commit_group;\n" ::: "memory")
#define CP_WAIT2  asm volatile("cp.async.wait_group 2;\n" ::: "memory")

__device__ __forceinline__ void ldsm_x4(unsigned* r, const void* p) {
    unsigned a = (unsigned)__cvta_generic_to_shared(p);
    asm volatile("ldmatrix.sync.aligned.m8n8.x4.shared.b16 {%0,%1,%2,%3}, [%4];"
        : "=r"(r[0]), "=r"(r[1]), "=r"(r[2]), "=r"(r[3]) : "r"(a));
}

__device__ __forceinline__ void mma_bf16(float* d, const unsigned* a, const unsigned* b) {
    asm volatile(
        "mma.sync.aligned.m16n8k16.row.col.f32.bf16.bf16.f32 "
        "{%0,%1,%2,%3}, {%4,%5,%6,%7}, {%8,%9}, {%0,%1,%2,%3};\n"
        : "+f"(d[0]), "+f"(d[1]), "+f"(d[2]), "+f"(d[3])
        : "r"(a[0]), "r"(a[1]), "r"(a[2]), "r"(a[3]), "r"(b[0]), "r"(b[1]));
}

__device__ __forceinline__ unsigned hadd2u(unsigned x, unsigned y) {
    __nv_bfloat162 a = *reinterpret_cast<__nv_bfloat162*>(&x);
    __nv_bfloat162 b = *reinterpret_cast<__nv_bfloat162*>(&y);
    __nv_bfloat162 r = __hadd2(a, b);
    return *reinterpret_cast<unsigned*>(&r);
}

__device__ __forceinline__ const void* addrA(const __nv_bfloat16* T, int r0,
                                             int m, int k0, int lane) {
    int grp = lane >> 3, lo = lane & 7;
    int row = r0 + m * 16 + ((grp & 1) ? 8 : 0) + lo;
    int col = k0 + ((grp >> 1) ? 8 : 0);
    return T + row * ROWSTRIDE + col;
}
__device__ __forceinline__ const void* addrB(const __nv_bfloat16* T, int c0,
                                             int np, int k0, int lane) {
    int grp = lane >> 3, lo = lane & 7;
    int row = c0 + np * 16 + ((grp >> 1) ? 8 : 0) + lo;
    int col = k0 + ((grp & 1) ? 8 : 0);
    return T + row * ROWSTRIDE + col;
}

__device__ __forceinline__ void load_chunk(size_t boff, int I, int J, int kc,
                                           int stage, int tid, char* raw) {
    const int k0 = kc * KC;
#pragma unroll
    for (int i = 0; i < 16; i++) {
        int e = tid + i * 128;                     // 0..2047
        int t = e >> 9;                            // tile: 0=cI 1=sI 2=cJ 3=sJ
        int q = e & 511;
        int row = q >> 3;
        int cp = q & 7;                            // 16B chunk within 128B row
        const __nv_bfloat16* gsrc = (t & 1) ? g_s : g_c;
        int grow = ((t < 2) ? I : J) + row;
        const __nv_bfloat16* src = gsrc + boff + (size_t)grow * FDIM + k0 + cp * 8;
        char* dst = raw + stage * STAGEBYTES + t * TILEBYTES + row * (ROWSTRIDE * 2) + cp * 16;
        cp_async16(dst, src);
    }
}

extern __shared__ char dynraw[];

__global__ void __launch_bounds__(128) k_gemm(const float* __restrict__ tgt_all) {
    __shared__ float red[4];
    char* raw = dynraw;
    const int bid = blockIdx.x;
    int b, ti, tj;
    if (bid < GOFF) {
        b = bid / NOFF;
        ti = c_opi[bid % NOFF];
        tj = c_opj[bid % NOFF];
    } else {
        int q = bid - GOFF;
        b = q / NDIA;
        ti = tj = q % NDIA;
    }
    const bool diag = (ti == tj);
    const int I = ti * TILE, J = tj * TILE;
    const int tid = threadIdx.x;
    const int w = tid >> 5, lane = tid & 31, g = lane >> 2, t4 = lane & 3;
    const int r0 = (w >> 1) * 32;
    const int c0 = (w & 1) * 32;
    const size_t boff = (size_t)b * CDIM * FDIM;

    float m1[2][4][4] = {}, m2[2][4][4] = {}, m3[2][4][4] = {};

    load_chunk(boff, I, J, 0, 0, tid, raw);
    CP_COMMIT;
    load_chunk(boff, I, J, 1, 1, tid, raw);
    CP_COMMIT;

    const int NK = FDIM / KC;                      // 32
    for (int kc = 0; kc < NK; kc++) {
        if (kc + 2 < NK) load_chunk(boff, I, J, kc + 2, (kc + 2) % NSTAGE, tid, raw);
        CP_COMMIT;
        CP_WAIT2;                                  // stage kc resident
        __syncthreads();
        const __nv_bfloat16* tb = reinterpret_cast<const __nv_bfloat16*>(
            raw + (kc % NSTAGE) * STAGEBYTES);
        const __nv_bfloat16* tCI = tb;
        const __nv_bfloat16* tSI = tb + TILEBYTES / 2;
        const __nv_bfloat16* tCJ = tb + TILEBYTES;
        const __nv_bfloat16* tSJ = tb + 3 * TILEBYTES / 2;
#pragma unroll
        for (int ks = 0; ks < 4; ks++) {
            const int k0 = ks * 16;
            unsigned aC[2][4], aS[2][4], aCS[2][4];
#pragma unroll
            for (int m = 0; m < 2; m++) {
                ldsm_x4(aC[m], addrA(tCI, r0, m, k0, lane));
                ldsm_x4(aS[m], addrA(tSI, r0, m, k0, lane));
#pragma unroll
                for (int r = 0; r < 4; r++) aCS[m][r] = hadd2u(aC[m][r], aS[m][r]);
            }
#pragma unroll
            for (int np = 0; np < 2; np++) {
                unsigned bC[4], bS[4], bCS[4];
                ldsm_x4(bS, addrB(tSJ, c0, np, k0, lane));
                ldsm_x4(bC, addrB(tCJ, c0, np, k0, lane));
#pragma unroll
                for (int r = 0; r < 4; r++) bCS[r] = hadd2u(bC[r], bS[r]);
#pragma unroll
                for (int m = 0; m < 2; m++)
#pragma unroll
                    for (int nn = 0; nn < 2; nn++) {
                        int n = np * 2 + nn;
                        mma_bf16(m1[m][n], aCS[m], bCS + 2 * nn);
                        mma_bf16(m2[m][n], aC[m], bS + 2 * nn);
                        if (!diag) mma_bf16(m3[m][n], aS[m], bC + 2 * nn);
                    }
            }
        }
        __syncthreads();
    }

    // Diag: stage m2 for transposed read (m3(r,c) = m2(c,r))
    float (*Ms)[TILE + 1] = reinterpret_cast<float(*)[TILE + 1]>(raw);
    if (diag) {
#pragma unroll
        for (int m = 0; m < 2; m++)
#pragma unroll
            for (int n = 0; n < 4; n++)
#pragma unroll
                for (int e = 0; e < 4; e++) {
                    int lr = r0 + m * 16 + g + ((e & 2) ? 8 : 0);
                    int lc = c0 + n * 8 + 2 * t4 + (e & 1);
                    Ms[lr][lc] = m2[m][n][e];
                }
    }
    __syncthreads();

    const float invF = 1.0f / (float)FDIM;
    const float* tgt = tgt_all + (size_t)b * CDIM * CDIM;
    float lsum = 0.f;
#pragma unroll
    for (int m = 0; m < 2; m++)
#pragma unroll
        for (int n = 0; n < 4; n++)
#pragma unroll
            for (int e = 0; e < 4; e++) {
                int lr = r0 + m * 16 + g + ((e & 2) ? 8 : 0);
                int lc = c0 + n * 8 + 2 * t4 + (e & 1);
                float v2 = m2[m][n][e];
                float v3 = diag ? Ms[lc][lr] : m3[m][n][e];
                float real = (m1[m][n][e] - v2 - v3) * invF;
                float imag = (v3 - v2) * invF;
                float pci = sqrtf(fmaf(real, real, fmaf(imag, imag, 1e-8f)));
                float d1 = pci - tgt[(I + lr) * CDIM + (J + lc)];
                lsum = fmaf(d1, d1, lsum);
                if (!diag) {
                    float d2 = pci - tgt[(J + lc) * CDIM + (I + lr)];
                    lsum = fmaf(d2, d2, lsum);
                }
            }
#pragma unroll
    for (int o = 16; o; o >>= 1) lsum += __shfl_xor_sync(0xffffffffu, lsum, o);
    if (lane == 0) red[w] = lsum;
    __syncthreads();
    if (tid == 0) g_cohp[bid] = red[0] + red[1] + red[2] + red[3];
}

// ---------------------------------------------------------------------------
// Kernel 3: combine partials (float4, fully unrolled, latency-minimal)
// ---------------------------------------------------------------------------
__global__ void __launch_bounds__(256) k_final(float* __restrict__ out) {
    const int t = threadIdx.x;
    const float4* p4 = reinterpret_cast<const float4*>(g_php);    // 512
    const float4* m4 = reinterpret_cast<const float4*>(g_magp);   // 256
    const float4* c4 = reinterpret_cast<const float4*>(g_cohp);   // 80
    float4 a = p4[t];
    float4 b = p4[t + 256];
    float4 mm = m4[t];
    float4 cc = (t < 80) ? c4[t] : make_float4(0.f, 0.f, 0.f, 0.f);
    float p = (a.x + a.y) + (a.z + a.w) + (b.x + b.y) + (b.z + b.w);
    float m = (mm.x + mm.y) + (mm.z + mm.w);
    float c = (cc.x + cc.y) + (cc.z + cc.w);
#pragma unroll
    for (int o = 16; o; o >>= 1) {
        p += __shfl_xor_sync(0xffffffffu, p, o);
        m += __shfl_xor_sync(0xffffffffu, m, o);
        c += __shfl_xor_sync(0xffffffffu, c, o);
    }
    __shared__ float sp[8], sm[8], sc[8];
    int w = t >> 5;
    if ((t & 31) == 0) { sp[w] = p; sm[w] = m; sc[w] = c; }
    __syncthreads();
    if (t == 0) {
        float P = 0.f, M = 0.f, C = 0.f;
#pragma unroll
        for (int i = 0; i < 8; i++) { P += sp[i]; M += sm[i]; C += sc[i]; }
        const float N1 = (float)NTOT;
        const float N2 = (float)(BDIM * CDIM * CDIM);
        float mag = M / N1;
        float ph  = P / N1;
        float coh = C / N2;
        out[0] = 1.0f * mag + 0.5f * ph + 0.3f * coh;
        out[1] = mag;
        out[2] = ph;
        out[3] = coh;
    }
}

// ---------------------------------------------------------------------------
extern "C" void kernel_launch(void* const* d_in, const int* in_sizes, int n_in,
                              void* d_out, int out_size) {
    const float4* mh = (const float4*)d_in[0];   // mag_hat
    const float4* ph = (const float4*)d_in[1];   // phase_hat
    const float4* mt = (const float4*)d_in[2];   // mag_target
    const float4* pt = (const float4*)d_in[3];   // phase_target
    const float*  pc = (const float*)d_in[4];    // pci_target
    float* out = (float*)d_out;

    static bool attr_set = false;
    if (!attr_set) {
        cudaFuncSetAttribute(k_gemm, cudaFuncAttributeMaxDynamicSharedMemorySize, SMEM_DYN);
        attr_set = true;
    }

    // k_phase saturates DRAM alone; then gemm (compute-bound) runs on stream 0
    // while k_mag (DRAM-only) rides under it on s2.
    k_phase<<<G1, T1>>>(ph, pt);
    cudaEventRecord(g_res.evPhase, 0);
    k_gemm<<<G2, 128, SMEM_DYN>>>(pc);
    cudaStreamWaitEvent(g_res.s2, g_res.evPhase, 0);
    k_mag<<<GM, T1, 0, g_res.s2>>>(mh, mt);
    cudaEventRecord(g_res.evJoin, g_res.s2);
    cudaStreamWaitEvent(0, g_res.evJoin, 0);
    k_final<<<1, 256>>>(out);
}

// round 17
// speedup vs baseline: 1.2531x; 1.2531x over previous
#include <cuda_runtime.h>
#include <cuda_bf16.h>
#include <cstdint>

// Problem dims
#define BDIM 32
#define CDIM 256
#define FDIM 2048
constexpr int NTOT = BDIM * CDIM * FDIM;          // 16,777,216
constexpr int N4 = NTOT / 4;                       // 4,194,304 float4s per tensor
constexpr int G1 = 2048;                           // k_phase grid
constexpr int T1 = 256;                            // k_phase block
constexpr int GM = 1024;                           // k_mag grid
constexpr int NOFF = 6;                            // off-diag pairs per batch
constexpr int NDIA = 4;                            // diag pairs per batch
constexpr int GOFF = BDIM * NOFF;                  // 192 off-diag blocks (first)
constexpr int G2 = BDIM * (NOFF + NDIA);           // 320 gemm blocks

// Scratch (device globals: allocation-free; 16B-aligned for float4 reduction)
__device__ __nv_bfloat16 g_c[NTOT];                // cos(phase_hat) bf16
__device__ __nv_bfloat16 g_s[NTOT];                // sin(phase_hat) bf16
__device__ __align__(16) float g_magp[GM];
__device__ __align__(16) float g_php[G1];
__device__ __align__(16) float g_cohp[G2];

__constant__ int c_opi[NOFF] = {0,0,0,1,1,2};
__constant__ int c_opj[NOFF] = {1,2,3,2,3,3};

// ---------------------------------------------------------------------------
// Stream/event plumbing (static-init; capture-safe fork/join)
// ---------------------------------------------------------------------------
struct OverlapRes {
    cudaStream_t s2;
    cudaEvent_t evPhase, evJoin;
    OverlapRes() {
        cudaStreamCreateWithFlags(&s2, cudaStreamNonBlocking);
        cudaEventCreateWithFlags(&evPhase, cudaEventDisableTiming);
        cudaEventCreateWithFlags(&evJoin, cudaEventDisableTiming);
    }
};
static OverlapRes g_res;

// ---------------------------------------------------------------------------
// Kernel 1a: phase loss + cos/sin scratch (HBM-bound, ~192MB)
// ---------------------------------------------------------------------------
__global__ void __launch_bounds__(T1) k_phase(
    const float4* __restrict__ ph, const float4* __restrict__ pt)
{
    int tid = blockIdx.x * T1 + threadIdx.x;
    const int stride = G1 * T1;
    float sp = 0.f;
    uint2* gc = reinterpret_cast<uint2*>(g_c);
    uint2* gs = reinterpret_cast<uint2*>(g_s);
#pragma unroll
    for (int i = 0; i < 8; i++) {
        int idx = tid + i * stride;
        float4 p = ph[idx], q = pt[idx];
        sp += 4.f - __cosf(p.x - q.x) - __cosf(p.y - q.y)
                  - __cosf(p.z - q.z) - __cosf(p.w - q.w);
        float s0, c0, s1, c1, s2, c2, s3, c3;
        __sincosf(p.x, &s0, &c0); __sincosf(p.y, &s1, &c1);
        __sincosf(p.z, &s2, &c2); __sincosf(p.w, &s3, &c3);
        __nv_bfloat162 hc0 = __floats2bfloat162_rn(c0, c1);
        __nv_bfloat162 hc1 = __floats2bfloat162_rn(c2, c3);
        __nv_bfloat162 hs0 = __floats2bfloat162_rn(s0, s1);
        __nv_bfloat162 hs1 = __floats2bfloat162_rn(s2, s3);
        gc[idx] = make_uint2(*reinterpret_cast<unsigned*>(&hc0),
                             *reinterpret_cast<unsigned*>(&hc1));
        gs[idx] = make_uint2(*reinterpret_cast<unsigned*>(&hs0),
                             *reinterpret_cast<unsigned*>(&hs1));
    }
#pragma unroll
    for (int o = 16; o; o >>= 1) sp += __shfl_xor_sync(0xffffffffu, sp, o);
    __shared__ float rp[8];
    int w = threadIdx.x >> 5;
    if ((threadIdx.x & 31) == 0) rp[w] = sp;
    __syncthreads();
    if (threadIdx.x == 0) {
        float b = 0.f;
#pragma unroll
        for (int i = 0; i < 8; i++) b += rp[i];
        g_php[blockIdx.x] = b;
    }
}

// ---------------------------------------------------------------------------
// Kernel 1b: mag MSE (pure DRAM; runs concurrently with k_gemm on stream s2)
// ---------------------------------------------------------------------------
__global__ void __launch_bounds__(T1) k_mag(
    const float4* __restrict__ mh, const float4* __restrict__ mt)
{
    int tid = blockIdx.x * T1 + threadIdx.x;
    const int stride = GM * T1;                    // 262144
    float sm = 0.f;
#pragma unroll
    for (int i = 0; i < 16; i++) {
        int idx = tid + i * stride;
        float4 a = mh[idx], b = mt[idx];
        float d0 = a.x - b.x, d1 = a.y - b.y, d2 = a.z - b.z, d3 = a.w - b.w;
        sm += d0 * d0 + d1 * d1 + d2 * d2 + d3 * d3;
    }
#pragma unroll
    for (int o = 16; o; o >>= 1) sm += __shfl_xor_sync(0xffffffffu, sm, o);
    __shared__ float rm[8];
    int w = threadIdx.x >> 5;
    if ((threadIdx.x & 31) == 0) rm[w] = sm;
    __syncthreads();
    if (threadIdx.x == 0) {
        float a = 0.f;
#pragma unroll
        for (int i = 0; i < 8; i++) a += rm[i];
        g_magp[blockIdx.x] = a;
    }
}

// ---------------------------------------------------------------------------
// Kernel 2: Gauss 3-mult symmetric-pair batched GEMM (bf16 mma.sync)
//   KC=64, 2-stage dynamic smem (73.7KB -> 2 CTAs/SM), off-diag-first.
// ---------------------------------------------------------------------------
#define KC 64
#define TILE 64
#define ROWSTRIDE 72                               // bf16 elems per smem row (128B + 16B pad)
#define TILEBYTES (TILE * ROWSTRIDE * 2)           // 9216
#define STAGEBYTES (4 * TILEBYTES)                 // 36864
#define SMEM_DYN (2 * STAGEBYTES)                  // 73728

__device__ __forceinline__ void cp_async16(void* smem, const void* gmem) {
    unsigned s = (unsigned)__cvta_generic_to_shared(smem);
    asm volatile("cp.async.cg.shared.global [%0], [%1], 16;\n" :: "r"(s), "l"(gmem));
}
#define CP_COMMIT asm volatile("cp.async.commit_group;\n" ::: "memory")
#define CP_WAIT1  asm volatile("cp.async.wait_group 1;\n" ::: "memory")

__device__ __forceinline__ void ldsm_x4(unsigned* r, const void* p) {
    unsigned a = (unsigned)__cvta_generic_to_shared(p);
    asm volatile("ldmatrix.sync.aligned.m8n8.x4.shared.b16 {%0,%1,%2,%3}, [%4];"
        : "=r"(r[0]), "=r"(r[1]), "=r"(r[2]), "=r"(r[3]) : "r"(a));
}

__device__ __forceinline__ void mma_bf16(float* d, const unsigned* a, const unsigned* b) {
    asm volatile(
        "mma.sync.aligned.m16n8k16.row.col.f32.bf16.bf16.f32 "
        "{%0,%1,%2,%3}, {%4,%5,%6,%7}, {%8,%9}, {%0,%1,%2,%3};\n"
        : "+f"(d[0]), "+f"(d[1]), "+f"(d[2]), "+f"(d[3])
        : "r"(a[0]), "r"(a[1]), "r"(a[2]), "r"(a[3]), "r"(b[0]), "r"(b[1]));
}

__device__ __forceinline__ unsigned hadd2u(unsigned x, unsigned y) {
    __nv_bfloat162 a = *reinterpret_cast<__nv_bfloat162*>(&x);
    __nv_bfloat162 b = *reinterpret_cast<__nv_bfloat162*>(&y);
    __nv_bfloat162 r = __hadd2(a, b);
    return *reinterpret_cast<unsigned*>(&r);
}

__device__ __forceinline__ const void* addrA(const __nv_bfloat16* T, int r0,
                                             int m, int k0, int lane) {
    int grp = lane >> 3, lo = lane & 7;
    int row = r0 + m * 16 + ((grp & 1) ? 8 : 0) + lo;
    int col = k0 + ((grp >> 1) ? 8 : 0);
    return T + row * ROWSTRIDE + col;
}
__device__ __forceinline__ const void* addrB(const __nv_bfloat16* T, int c0,
                                             int np, int k0, int lane) {
    int grp = lane >> 3, lo = lane & 7;
    int row = c0 + np * 16 + ((grp >> 1) ? 8 : 0) + lo;
    int col = k0 + ((grp & 1) ? 8 : 0);
    return T + row * ROWSTRIDE + col;
}

__device__ __forceinline__ void load_chunk(size_t boff, int I, int J, int kc,
                                           int stage, int tid, char* raw) {
    const int k0 = kc * KC;
#pragma unroll
    for (int i = 0; i < 16; i++) {
        int e = tid + i * 128;                     // 0..2047
        int t = e >> 9;                            // tile: 0=cI 1=sI 2=cJ 3=sJ
        int q = e & 511;
        int row = q >> 3;
        int cp = q & 7;                            // 16B chunk within 128B row
        const __nv_bfloat16* gsrc = (t & 1) ? g_s : g_c;
        int grow = ((t < 2) ? I : J) + row;
        const __nv_bfloat16* src = gsrc + boff + (size_t)grow * FDIM + k0 + cp * 8;
        char* dst = raw + stage * STAGEBYTES + t * TILEBYTES + row * (ROWSTRIDE * 2) + cp * 16;
        cp_async16(dst, src);
    }
}

extern __shared__ char dynraw[];

__global__ void __launch_bounds__(128) k_gemm(const float* __restrict__ tgt_all) {
    __shared__ float red[4];
    char* raw = dynraw;
    const int bid = blockIdx.x;
    int b, ti, tj;
    if (bid < GOFF) {
        b = bid / NOFF;
        ti = c_opi[bid % NOFF];
        tj = c_opj[bid % NOFF];
    } else {
        int q = bid - GOFF;
        b = q / NDIA;
        ti = tj = q % NDIA;
    }
    const bool diag = (ti == tj);
    const int I = ti * TILE, J = tj * TILE;
    const int tid = threadIdx.x;
    const int w = tid >> 5, lane = tid & 31, g = lane >> 2, t4 = lane & 3;
    const int r0 = (w >> 1) * 32;
    const int c0 = (w & 1) * 32;
    const size_t boff = (size_t)b * CDIM * FDIM;

    float m1[2][4][4] = {}, m2[2][4][4] = {}, m3[2][4][4] = {};

    load_chunk(boff, I, J, 0, 0, tid, raw);
    CP_COMMIT;

    const int NK = FDIM / KC;                      // 32
    for (int kc = 0; kc < NK; kc++) {
        if (kc + 1 < NK) load_chunk(boff, I, J, kc + 1, (kc + 1) & 1, tid, raw);
        CP_COMMIT;
        CP_WAIT1;
        __syncthreads();
        const __nv_bfloat16* tb = reinterpret_cast<const __nv_bfloat16*>(raw + (kc & 1) * STAGEBYTES);
        const __nv_bfloat16* tCI = tb;
        const __nv_bfloat16* tSI = tb + TILEBYTES / 2;
        const __nv_bfloat16* tCJ = tb + TILEBYTES;
        const __nv_bfloat16* tSJ = tb + 3 * TILEBYTES / 2;
#pragma unroll
        for (int ks = 0; ks < 4; ks++) {
            const int k0 = ks * 16;
            unsigned aC[2][4], aS[2][4], aCS[2][4];
#pragma unroll
            for (int m = 0; m < 2; m++) {
                ldsm_x4(aC[m], addrA(tCI, r0, m, k0, lane));
                ldsm_x4(aS[m], addrA(tSI, r0, m, k0, lane));
#pragma unroll
                for (int r = 0; r < 4; r++) aCS[m][r] = hadd2u(aC[m][r], aS[m][r]);
            }
#pragma unroll
            for (int np = 0; np < 2; np++) {
                unsigned bC[4], bS[4], bCS[4];
                ldsm_x4(bS, addrB(tSJ, c0, np, k0, lane));
                ldsm_x4(bC, addrB(tCJ, c0, np, k0, lane));
#pragma unroll
                for (int r = 0; r < 4; r++) bCS[r] = hadd2u(bC[r], bS[r]);
#pragma unroll
                for (int m = 0; m < 2; m++)
#pragma unroll
                    for (int nn = 0; nn < 2; nn++) {
                        int n = np * 2 + nn;
                        mma_bf16(m1[m][n], aCS[m], bCS + 2 * nn);
                        mma_bf16(m2[m][n], aC[m], bS + 2 * nn);
                        if (!diag) mma_bf16(m3[m][n], aS[m], bC + 2 * nn);
                    }
            }
        }
        __syncthreads();
    }

    // Diag: stage m2 for transposed read (m3(r,c) = m2(c,r))
    float (*Ms)[TILE + 1] = reinterpret_cast<float(*)[TILE + 1]>(raw);
    if (diag) {
#pragma unroll
        for (int m = 0; m < 2; m++)
#pragma unroll
            for (int n = 0; n < 4; n++)
#pragma unroll
                for (int e = 0; e < 4; e++) {
                    int lr = r0 + m * 16 + g + ((e & 2) ? 8 : 0);
                    int lc = c0 + n * 8 + 2 * t4 + (e & 1);
                    Ms[lr][lc] = m2[m][n][e];
                }
    }
    __syncthreads();

    const float invF = 1.0f / (float)FDIM;
    const float* tgt = tgt_all + (size_t)b * CDIM * CDIM;
    float lsum = 0.f;
#pragma unroll
    for (int m = 0; m < 2; m++)
#pragma unroll
        for (int n = 0; n < 4; n++)
#pragma unroll
            for (int e = 0; e < 4; e++) {
                int lr = r0 + m * 16 + g + ((e & 2) ? 8 : 0);
                int lc = c0 + n * 8 + 2 * t4 + (e & 1);
                float v2 = m2[m][n][e];
                float v3 = diag ? Ms[lc][lr] : m3[m][n][e];
                float real = (m1[m][n][e] - v2 - v3) * invF;
                float imag = (v3 - v2) * invF;
                float pci = sqrtf(fmaf(real, real, fmaf(imag, imag, 1e-8f)));
                float d1 = pci - tgt[(I + lr) * CDIM + (J + lc)];
                lsum = fmaf(d1, d1, lsum);
                if (!diag) {
                    float d2 = pci - tgt[(J + lc) * CDIM + (I + lr)];
                    lsum = fmaf(d2, d2, lsum);
                }
            }
#pragma unroll
    for (int o = 16; o; o >>= 1) lsum += __shfl_xor_sync(0xffffffffu, lsum, o);
    if (lane == 0) red[w] = lsum;
    __syncthreads();
    if (tid == 0) g_cohp[bid] = red[0] + red[1] + red[2] + red[3];
}

// ---------------------------------------------------------------------------
// Kernel 3: combine partials (float4, fully unrolled, latency-minimal)
// ---------------------------------------------------------------------------
__global__ void __launch_bounds__(256) k_final(float* __restrict__ out) {
    const int t = threadIdx.x;
    const float4* p4 = reinterpret_cast<const float4*>(g_php);    // 512
    const float4* m4 = reinterpret_cast<const float4*>(g_magp);   // 256
    const float4* c4 = reinterpret_cast<const float4*>(g_cohp);   // 80
    float4 a = p4[t];
    float4 b = p4[t + 256];
    float4 mm = m4[t];
    float4 cc = (t < 80) ? c4[t] : make_float4(0.f, 0.f, 0.f, 0.f);
    float p = (a.x + a.y) + (a.z + a.w) + (b.x + b.y) + (b.z + b.w);
    float m = (mm.x + mm.y) + (mm.z + mm.w);
    float c = (cc.x + cc.y) + (cc.z + cc.w);
#pragma unroll
    for (int o = 16; o; o >>= 1) {
        p += __shfl_xor_sync(0xffffffffu, p, o);
        m += __shfl_xor_sync(0xffffffffu, m, o);
        c += __shfl_xor_sync(0xffffffffu, c, o);
    }
    __shared__ float sp[8], sm[8], sc[8];
    int w = t >> 5;
    if ((t & 31) == 0) { sp[w] = p; sm[w] = m; sc[w] = c; }
    __syncthreads();
    if (t == 0) {
        float P = 0.f, M = 0.f, C = 0.f;
#pragma unroll
        for (int i = 0; i < 8; i++) { P += sp[i]; M += sm[i]; C += sc[i]; }
        const float N1 = (float)NTOT;
        const float N2 = (float)(BDIM * CDIM * CDIM);
        float mag = M / N1;
        float ph  = P / N1;
        float coh = C / N2;
        out[0] = 1.0f * mag + 0.5f * ph + 0.3f * coh;
        out[1] = mag;
        out[2] = ph;
        out[3] = coh;
    }
}

// ---------------------------------------------------------------------------
extern "C" void kernel_launch(void* const* d_in, const int* in_sizes, int n_in,
                              void* d_out, int out_size) {
    const float4* mh = (const float4*)d_in[0];   // mag_hat
    const float4* ph = (const float4*)d_in[1];   // phase_hat
    const float4* mt = (const float4*)d_in[2];   // mag_target
    const float4* pt = (const float4*)d_in[3];   // phase_target
    const float*  pc = (const float*)d_in[4];    // pci_target
    float* out = (float*)d_out;

    static bool attr_set = false;
    if (!attr_set) {
        cudaFuncSetAttribute(k_gemm, cudaFuncAttributeMaxDynamicSharedMemorySize, SMEM_DYN);
        attr_set = true;
    }

    // k_phase saturates DRAM alone; then gemm (compute-bound) runs on stream 0
    // while k_mag (DRAM-only) rides under it on s2.
    k_phase<<<G1, T1>>>(ph, pt);
    cudaEventRecord(g_res.evPhase, 0);
    k_gemm<<<G2, 128, SMEM_DYN>>>(pc);
    cudaStreamWaitEvent(g_res.s2, g_res.evPhase, 0);
    k_mag<<<GM, T1, 0, g_res.s2>>>(mh, mt);
    cudaEventRecord(g_res.evJoin, g_res.s2);
    cudaStreamWaitEvent(0, g_res.evJoin, 0);
    k_final<<<1, 256>>>(out);
}